// round 6
// baseline (speedup 1.0000x reference)
#include <cuda_runtime.h>
#include <cuda_fp16.h>
#include <cstdint>
#include <math.h>

// Problem constants (fixed shapes from setup_inputs)
#define BATCH   4
#define N1      4096
#define N2      16384
#define D1      512
#define D2      256
#define DO      256
#define M1      (BATCH * N1)   // 16384
#define M2      (BATCH * N2)   // 65536

// ---------------------------------------------------------------------------
// Device scratch (allocation-free rule: __device__ globals)
// ---------------------------------------------------------------------------
__device__ float g_feats1[M1 * DO];                         // 16 MB
__device__ __align__(16) __half gA1f[M1 * D1];              // 16 MB
__device__ __align__(16) __half gA2f[M2 * D2];              // 32 MB
__device__ __align__(16) __half gW1f[DO * D1];
__device__ __align__(16) __half gW2f[DO * D2];

// ---------------------------------------------------------------------------
// Helpers
// ---------------------------------------------------------------------------
__device__ __forceinline__ uint32_t smem_u32(const void* p) {
    uint32_t a;
    asm("{ .reg .u64 t; cvta.to.shared.u64 t, %1; cvt.u32.u64 %0, t; }"
        : "=r"(a) : "l"(p));
    return a;
}

#define SWZ(o) ((o) ^ (((o) >> 3) & 0x70))

#define CP16(dst, src) \
    asm volatile("cp.async.cg.shared.global [%0], [%1], 16;" :: "r"(dst), "l"(src) : "memory")
#define CP_COMMIT() asm volatile("cp.async.commit_group;" ::: "memory")
#define CP_WAIT0()  asm volatile("cp.async.wait_group 0;" ::: "memory")
#define CP_WAIT1()  asm volatile("cp.async.wait_group 1;" ::: "memory")

__device__ __forceinline__ void ldsm4(uint32_t r[4], uint32_t addr) {
    asm volatile("ldmatrix.sync.aligned.m8n8.x4.shared.b16 {%0,%1,%2,%3}, [%4];"
        : "=r"(r[0]), "=r"(r[1]), "=r"(r[2]), "=r"(r[3]) : "r"(addr));
}
__device__ __forceinline__ void ldsm2(uint32_t r[2], uint32_t addr) {
    asm volatile("ldmatrix.sync.aligned.m8n8.x2.shared.b16 {%0,%1}, [%2];"
        : "=r"(r[0]), "=r"(r[1]) : "r"(addr));
}
__device__ __forceinline__ void mma_f16(float d[4], const uint32_t a[4], const uint32_t b[2]) {
    asm volatile("mma.sync.aligned.m16n8k16.row.col.f32.f16.f16.f32 "
        "{%0,%1,%2,%3}, {%4,%5,%6,%7}, {%8,%9}, {%0,%1,%2,%3};"
        : "+f"(d[0]), "+f"(d[1]), "+f"(d[2]), "+f"(d[3])
        : "r"(a[0]), "r"(a[1]), "r"(a[2]), "r"(a[3]), "r"(b[0]), "r"(b[1]));
}

// ---------------------------------------------------------------------------
// fp32 -> fp16 convert (round-to-nearest)
// ---------------------------------------------------------------------------
__global__ __launch_bounds__(256)
void cvt_half_kernel(const float* __restrict__ x, __half* __restrict__ y, int n4)
{
    int i = blockIdx.x * blockDim.x + threadIdx.x;
    int stride = gridDim.x * blockDim.x;
    for (; i < n4; i += stride) {
        float4 v = ((const float4*)x)[i];
        __half2 h0 = __floats2half2_rn(v.x, v.y);
        __half2 h1 = __floats2half2_rn(v.z, v.w);
        ((__half2*)y)[2 * i + 0] = h0;
        ((__half2*)y)[2 * i + 1] = h1;
    }
}

// ---------------------------------------------------------------------------
// fp16 single-pass mma.sync GEMM + BN + ReLU.
// C[m,n] = relu((sum_k A[m,k]W[n,k] + bias[n]) * s[n] + sh[n])
// fp32 register accumulators.
// CTA tile 128x128, K-chunk 64 fp16 (128B SW128 rows), 8 warps (2x4),
// warp tile 64x32 (4x4 m16n8k16). Double-buffered cp.async.
// ---------------------------------------------------------------------------
#define STAGE 32768u     // A 16K | B 16K
#define GEMM_DSMEM (2 * 32768 + 1024)

__device__ __forceinline__ void load_chunk(int tid, int bm, int bn, int K,
                                           uint32_t base, int c,
                                           const __half* __restrict__ A,
                                           const __half* __restrict__ B)
{
    uint32_t sb = base + (uint32_t)(c & 1) * STAGE;
    int kc = c << 6;
    // A: 128 rows x 64 fp16 (128B rows)
    for (int i = tid; i < 1024; i += 256) {
        int row = i >> 3, seg = i & 7;
        uint32_t off = SWZ((uint32_t)(row * 128 + seg * 16));
        CP16(sb + off, (const char*)(A + (size_t)(bm + row) * K + kc + seg * 8));
    }
    // B: 128 n-rows x 64 fp16
    for (int i = tid; i < 1024; i += 256) {
        int row = i >> 3, seg = i & 7;
        uint32_t off = SWZ((uint32_t)(row * 128 + seg * 16));
        CP16(sb + 16384u + off, (const char*)(B + (size_t)(bn + row) * K + kc + seg * 8));
    }
    CP_COMMIT();
}

__global__ __launch_bounds__(256)
void gemm_mma_kernel(const __half* __restrict__ A,
                     const __half* __restrict__ B,
                     const float* __restrict__ bias,
                     const float* __restrict__ gamma,
                     const float* __restrict__ beta,
                     const float* __restrict__ mean,
                     const float* __restrict__ var,
                     float* __restrict__ C, int K)
{
    extern __shared__ char dsm[];
    __shared__ float sScale[128], sShift[128], sBias[128];

    const int tid  = threadIdx.x;
    const int wid  = tid >> 5;
    const int lane = tid & 31;
    const int wm   = wid >> 2;        // 0..1
    const int wn   = wid & 3;         // 0..3
    const int bm   = blockIdx.x * 128;
    const int bn   = blockIdx.y * 128;
    const int NC   = K >> 6;
    uint32_t base  = (smem_u32(dsm) + 1023u) & ~1023u;

    if (tid < 128) {
        int n = bn + tid;
        float sc = gamma[n] * rsqrtf(var[n] + 1e-5f);
        sScale[tid] = sc;
        sShift[tid] = beta[n] - mean[n] * sc;
        sBias[tid]  = bias[n];
    }

    float acc[4][4][4];
#pragma unroll
    for (int mi = 0; mi < 4; mi++)
#pragma unroll
        for (int ni = 0; ni < 4; ni++)
#pragma unroll
            for (int e = 0; e < 4; e++) acc[mi][ni][e] = 0.f;

    load_chunk(tid, bm, bn, K, base, 0, A, B);

    // Lane-local ldmatrix source coordinates (pre-swizzle)
    const int arow  = wm * 64 + (lane & 15);
    const int acolb = (lane >> 4) * 16;
    const int l16   = lane & 15;
    const int brow  = wn * 32 + (l16 & 7);
    const int bcolb = (l16 >> 3) * 16;

    for (int c = 0; c < NC; c++) {
        if (c + 1 < NC) {
            load_chunk(tid, bm, bn, K, base, c + 1, A, B);
            CP_WAIT1();
        } else {
            CP_WAIT0();
        }
        __syncthreads();

        uint32_t sb = base + (uint32_t)(c & 1) * STAGE;
        uint32_t sA = sb, sB = sb + 16384u;

#pragma unroll
        for (int kk = 0; kk < 4; kk++) {
            uint32_t af[4][4], bf[4][2];
#pragma unroll
            for (int mi = 0; mi < 4; mi++) {
                uint32_t off = SWZ((uint32_t)((arow + mi * 16) * 128 + kk * 32 + acolb));
                ldsm4(af[mi], sA + off);
            }
#pragma unroll
            for (int ni = 0; ni < 4; ni++) {
                uint32_t off = SWZ((uint32_t)((brow + ni * 8) * 128 + kk * 32 + bcolb));
                ldsm2(bf[ni], sB + off);
            }
#pragma unroll
            for (int mi = 0; mi < 4; mi++)
#pragma unroll
                for (int ni = 0; ni < 4; ni++)
                    mma_f16(acc[mi][ni], af[mi], bf[ni]);
        }
        __syncthreads();
    }

    // Epilogue: bias + BN + ReLU, float2 stores
    const int tr = lane >> 2, tq = lane & 3;
#pragma unroll
    for (int mi = 0; mi < 4; mi++) {
        int row0 = bm + wm * 64 + mi * 16 + tr;
#pragma unroll
        for (int ni = 0; ni < 4; ni++) {
            int lc = wn * 32 + ni * 8 + 2 * tq;
            int col = bn + lc;
            float s0 = sScale[lc],     s1 = sScale[lc + 1];
            float h0 = sShift[lc],     h1 = sShift[lc + 1];
            float bb0 = sBias[lc],     bb1 = sBias[lc + 1];
            float2 v0, v1;
            v0.x = fmaxf((acc[mi][ni][0] + bb0) * s0 + h0, 0.f);
            v0.y = fmaxf((acc[mi][ni][1] + bb1) * s1 + h1, 0.f);
            v1.x = fmaxf((acc[mi][ni][2] + bb0) * s0 + h0, 0.f);
            v1.y = fmaxf((acc[mi][ni][3] + bb1) * s1 + h1, 0.f);
            *(float2*)&C[(size_t)row0 * DO + col]       = v0;
            *(float2*)&C[(size_t)(row0 + 8) * DO + col] = v1;
        }
    }
}

// ---------------------------------------------------------------------------
// Fused 3-NN + inverse-distance-weighted gather + accumulate (proven R1).
// ---------------------------------------------------------------------------
#define KNN_THREADS 256
#define KNN_SMEM (N1 * 16 + KNN_THREADS * 3 * 4 * 2)

__global__ __launch_bounds__(KNN_THREADS)
void knn_interp_kernel(const float* __restrict__ xyz2,
                       const float* __restrict__ xyz1,
                       float* __restrict__ out)
{
    extern __shared__ float smem[];
    float4* sx = (float4*)smem;
    float*  sw = smem + N1 * 4;
    int*    si = (int*)(sw + KNN_THREADS * 3);

    const int b   = blockIdx.y;
    const int tid = threadIdx.x;
    const int t   = blockIdx.x * KNN_THREADS + tid;

    for (int i = tid; i < N1; i += KNN_THREADS) {
        const float* p = &xyz1[((size_t)b * N1 + i) * 3];
        float x = p[0], y = p[1], z = p[2];
        sx[i] = make_float4(-2.f * x, -2.f * y, -2.f * z, x * x + y * y + z * z);
    }
    __syncthreads();

    const float* tp = &xyz2[((size_t)b * N2 + t) * 3];
    const float txx = tp[0], tyy = tp[1], tzz = tp[2];

    float k0 = 3.4e38f, k1 = 3.4e38f, k2 = 3.4e38f;
    int   i0 = 0, i1 = 0, i2 = 0;

#pragma unroll 4
    for (int s = 0; s < N1; s++) {
        float4 p = sx[s];
        float key = fmaf(p.x, txx, fmaf(p.y, tyy, fmaf(p.z, tzz, p.w)));
        if (key < k2) {
            if (key < k0)      { k2 = k1; i2 = i1; k1 = k0; i1 = i0; k0 = key; i0 = s; }
            else if (key < k1) { k2 = k1; i2 = i1; k1 = key; i1 = s; }
            else               { k2 = key; i2 = s; }
        }
    }

    float tt = txx * txx + tyy * tyy + tzz * tzz;
    float d0 = k0 + tt, d1 = k1 + tt, d2 = k2 + tt;
    float w0 = 1.f / (d0 + 1e-8f);
    float w1 = 1.f / (d1 + 1e-8f);
    float w2 = 1.f / (d2 + 1e-8f);
    float inv = 1.f / (w0 + w1 + w2);
    sw[tid * 3 + 0] = w0 * inv;
    sw[tid * 3 + 1] = w1 * inv;
    sw[tid * 3 + 2] = w2 * inv;
    si[tid * 3 + 0] = i0;
    si[tid * 3 + 1] = i1;
    si[tid * 3 + 2] = i2;
    __syncthreads();

    const int warp = tid >> 5, lane = tid & 31;
    const float* fb = g_feats1 + (size_t)b * N1 * DO;

    for (int j = 0; j < 32; j++) {
        int local = warp * 32 + j;
        float ww0 = sw[local * 3 + 0];
        float ww1 = sw[local * 3 + 1];
        float ww2 = sw[local * 3 + 2];
        int   a0  = si[local * 3 + 0];
        int   a1  = si[local * 3 + 1];
        int   a2  = si[local * 3 + 2];
        const float4* f0 = (const float4*)(fb + (size_t)a0 * DO);
        const float4* f1 = (const float4*)(fb + (size_t)a1 * DO);
        const float4* f2 = (const float4*)(fb + (size_t)a2 * DO);
        int tgt = blockIdx.x * KNN_THREADS + local;
        float4* o = (float4*)(out + ((size_t)b * N2 + tgt) * DO);
#pragma unroll
        for (int c = 0; c < 2; c++) {
            int ci = lane * 2 + c;
            float4 va = f0[ci], vb = f1[ci], vc = f2[ci], vo = o[ci];
            vo.x += ww0 * va.x + ww1 * vb.x + ww2 * vc.x;
            vo.y += ww0 * va.y + ww1 * vb.y + ww2 * vc.y;
            vo.z += ww0 * va.z + ww1 * vb.z + ww2 * vc.z;
            vo.w += ww0 * va.w + ww1 * vb.w + ww2 * vc.w;
            o[ci] = vo;
        }
    }
}

// ---------------------------------------------------------------------------
extern "C" void kernel_launch(void* const* d_in, const int* in_sizes, int n_in,
                              void* d_out, int out_size)
{
    const float* xyz1    = (const float*)d_in[0];
    const float* points1 = (const float*)d_in[1];
    const float* xyz2    = (const float*)d_in[2];
    const float* points2 = (const float*)d_in[3];
    const float* W1  = (const float*)d_in[4];
    const float* b1  = (const float*)d_in[5];
    const float* g1  = (const float*)d_in[6];
    const float* be1 = (const float*)d_in[7];
    const float* m1  = (const float*)d_in[8];
    const float* v1  = (const float*)d_in[9];
    const float* W2  = (const float*)d_in[10];
    const float* b2  = (const float*)d_in[11];
    const float* g2  = (const float*)d_in[12];
    const float* be2 = (const float*)d_in[13];
    const float* m2  = (const float*)d_in[14];
    const float* v2  = (const float*)d_in[15];
    float* out = (float*)d_out;

    float* feats1;
    __half *a1f, *a2f, *w1f, *w2f;
    cudaGetSymbolAddress((void**)&feats1, g_feats1);
    cudaGetSymbolAddress((void**)&a1f, gA1f);
    cudaGetSymbolAddress((void**)&a2f, gA2f);
    cudaGetSymbolAddress((void**)&w1f, gW1f);
    cudaGetSymbolAddress((void**)&w2f, gW2f);

    // fp32 -> fp16 converts
    cvt_half_kernel<<<2048, 256>>>(points1, a1f, M1 * D1 / 4);
    cvt_half_kernel<<<4096, 256>>>(points2, a2f, M2 * D2 / 4);
    cvt_half_kernel<<<128,  256>>>(W1, w1f, DO * D1 / 4);
    cvt_half_kernel<<<64,   256>>>(W2, w2f, DO * D2 / 4);

    cudaFuncSetAttribute(gemm_mma_kernel,
                         cudaFuncAttributeMaxDynamicSharedMemorySize, GEMM_DSMEM);

    // K1: feats1 = relu(bn(points1 @ W1^T + b1))   [16384, 256]
    {
        dim3 grid(M1 / 128, DO / 128);
        gemm_mma_kernel<<<grid, 256, GEMM_DSMEM>>>(a1f, w1f,
                                                   b1, g1, be1, m1, v1,
                                                   feats1, D1);
    }
    // K2: out = relu(bn(points2 @ W2^T + b2))      [65536, 256]
    {
        dim3 grid(M2 / 128, DO / 128);
        gemm_mma_kernel<<<grid, 256, GEMM_DSMEM>>>(a2f, w2f,
                                                   b2, g2, be2, m2, v2,
                                                   out, D2);
    }
    // K3: out += interpolate3(xyz2 <- xyz1, feats1)
    cudaFuncSetAttribute(knn_interp_kernel,
                         cudaFuncAttributeMaxDynamicSharedMemorySize, KNN_SMEM);
    dim3 grid(N2 / KNN_THREADS, BATCH);
    knn_interp_kernel<<<grid, KNN_THREADS, KNN_SMEM>>>(xyz2, xyz1, out);
}

// round 7
// speedup vs baseline: 1.5000x; 1.5000x over previous
#include <cuda_runtime.h>
#include <cuda_fp16.h>
#include <cstdint>
#include <math.h>

// Problem constants (fixed shapes from setup_inputs)
#define BATCH   4
#define N1      4096
#define N2      16384
#define D1      512
#define D2      256
#define DO      256
#define M1      (BATCH * N1)   // 16384
#define M2      (BATCH * N2)   // 65536

// ---------------------------------------------------------------------------
// Device scratch (allocation-free rule: __device__ globals)
// ---------------------------------------------------------------------------
__device__ float g_feats1[M1 * DO];                         // 16 MB
__device__ __align__(16) __half gA1f[M1 * D1];              // 16 MB
__device__ __align__(16) __half gA2f[M2 * D2];              // 32 MB
__device__ __align__(16) __half gW1f[DO * D1];
__device__ __align__(16) __half gW2f[DO * D2];

// ---------------------------------------------------------------------------
// Helpers
// ---------------------------------------------------------------------------
__device__ __forceinline__ uint32_t smem_u32(const void* p) {
    uint32_t a;
    asm("{ .reg .u64 t; cvta.to.shared.u64 t, %1; cvt.u32.u64 %0, t; }"
        : "=r"(a) : "l"(p));
    return a;
}

#define SWZ(o) ((o) ^ (((o) >> 3) & 0x70))

#define CP16(dst, src) \
    asm volatile("cp.async.cg.shared.global [%0], [%1], 16;" :: "r"(dst), "l"(src) : "memory")
#define CP_COMMIT() asm volatile("cp.async.commit_group;" ::: "memory")
#define CP_WAIT0()  asm volatile("cp.async.wait_group 0;" ::: "memory")
#define CP_WAIT1()  asm volatile("cp.async.wait_group 1;" ::: "memory")

__device__ __forceinline__ void ldsm4(uint32_t r[4], uint32_t addr) {
    asm volatile("ldmatrix.sync.aligned.m8n8.x4.shared.b16 {%0,%1,%2,%3}, [%4];"
        : "=r"(r[0]), "=r"(r[1]), "=r"(r[2]), "=r"(r[3]) : "r"(addr));
}
__device__ __forceinline__ void mma_f16(float d[4], const uint32_t a[4], const uint32_t b[2]) {
    asm volatile("mma.sync.aligned.m16n8k16.row.col.f32.f16.f16.f32 "
        "{%0,%1,%2,%3}, {%4,%5,%6,%7}, {%8,%9}, {%0,%1,%2,%3};"
        : "+f"(d[0]), "+f"(d[1]), "+f"(d[2]), "+f"(d[3])
        : "r"(a[0]), "r"(a[1]), "r"(a[2]), "r"(a[3]), "r"(b[0]), "r"(b[1]));
}

// ---------------------------------------------------------------------------
// fp32 -> fp16 convert (round-to-nearest)
// ---------------------------------------------------------------------------
__global__ __launch_bounds__(256)
void cvt_half_kernel(const float* __restrict__ x, __half* __restrict__ y, int n4)
{
    int i = blockIdx.x * blockDim.x + threadIdx.x;
    int stride = gridDim.x * blockDim.x;
    for (; i < n4; i += stride) {
        float4 v = ((const float4*)x)[i];
        __half2 h0 = __floats2half2_rn(v.x, v.y);
        __half2 h1 = __floats2half2_rn(v.z, v.w);
        ((__half2*)y)[2 * i + 0] = h0;
        ((__half2*)y)[2 * i + 1] = h1;
    }
}

// ---------------------------------------------------------------------------
// fp16 mma.sync GEMM + BN + ReLU, CTA tile 128x256 (full DO in one pass).
// C[m,n] = relu((sum_k A[m,k]W[n,k] + bias[n]) * s[n] + sh[n])
// 512 threads = 16 warps (4 x 4), warp tile 32x64 (2x8 m16n8k16 frags).
// K-chunk 64 fp16 (128B SW128 rows). Double-buffered cp.async.
// Stage: A 16KB | B 32KB = 48KB; 2 stages.
// ---------------------------------------------------------------------------
#define STAGE 49152u
#define GEMM_DSMEM (2 * 49152 + 1024)

__device__ __forceinline__ void load_chunk(int tid, int bm, int K,
                                           uint32_t base, int c,
                                           const __half* __restrict__ A,
                                           const __half* __restrict__ B)
{
    uint32_t sb = base + (uint32_t)(c & 1) * STAGE;
    int kc = c << 6;
    // A: 128 rows x 64 fp16 (128B rows), 1024 cp16 -> 2 per thread
    for (int i = tid; i < 1024; i += 512) {
        int row = i >> 3, seg = i & 7;
        uint32_t off = SWZ((uint32_t)(row * 128 + seg * 16));
        CP16(sb + off, (const char*)(A + (size_t)(bm + row) * K + kc + seg * 8));
    }
    // B: 256 n-rows x 64 fp16, 2048 cp16 -> 4 per thread
    for (int i = tid; i < 2048; i += 512) {
        int row = i >> 3, seg = i & 7;
        uint32_t off = SWZ((uint32_t)(row * 128 + seg * 16));
        CP16(sb + 16384u + off, (const char*)(B + (size_t)row * K + kc + seg * 8));
    }
    CP_COMMIT();
}

__global__ __launch_bounds__(512, 1)
void gemm_mma_kernel(const __half* __restrict__ A,
                     const __half* __restrict__ B,
                     const float* __restrict__ bias,
                     const float* __restrict__ gamma,
                     const float* __restrict__ beta,
                     const float* __restrict__ mean,
                     const float* __restrict__ var,
                     float* __restrict__ C, int K)
{
    extern __shared__ char dsm[];
    __shared__ float sScale[DO], sShift[DO], sBias[DO];

    const int tid  = threadIdx.x;
    const int wid  = tid >> 5;
    const int lane = tid & 31;
    const int wm   = wid >> 2;        // 0..3 -> 32-row slab
    const int wn   = wid & 3;         // 0..3 -> 64-col slab
    const int bm   = blockIdx.x * 128;
    const int NC   = K >> 6;
    uint32_t base  = (smem_u32(dsm) + 1023u) & ~1023u;

    if (tid < DO) {
        float sc = gamma[tid] * rsqrtf(var[tid] + 1e-5f);
        sScale[tid] = sc;
        sShift[tid] = beta[tid] - mean[tid] * sc;
        sBias[tid]  = bias[tid];
    }

    float acc[2][8][4];
#pragma unroll
    for (int mi = 0; mi < 2; mi++)
#pragma unroll
        for (int ni = 0; ni < 8; ni++)
#pragma unroll
            for (int e = 0; e < 4; e++) acc[mi][ni][e] = 0.f;

    load_chunk(tid, bm, K, base, 0, A, B);

    // ldmatrix lane-source coordinates (pre-swizzle)
    const int arow  = wm * 32 + (lane & 15);      // + mi*16
    const int acolb = (lane >> 4) * 16;           // k-byte within 32B half
    const int g     = lane >> 3;                  // 0..3
    const int bnrow = (g >> 1) * 8 + (lane & 7);  // n offset within 16-row pair
    const int bkb   = (g & 1) * 16;               // k-byte

    for (int c = 0; c < NC; c++) {
        if (c + 1 < NC) {
            load_chunk(tid, bm, K, base, c + 1, A, B);
            CP_WAIT1();
        } else {
            CP_WAIT0();
        }
        __syncthreads();

        uint32_t sb = base + (uint32_t)(c & 1) * STAGE;
        uint32_t sA = sb, sB = sb + 16384u;

#pragma unroll
        for (int kk = 0; kk < 4; kk++) {
            uint32_t af[2][4], bf[8][2];
#pragma unroll
            for (int mi = 0; mi < 2; mi++) {
                uint32_t off = SWZ((uint32_t)((arow + mi * 16) * 128 + kk * 32 + acolb));
                ldsm4(af[mi], sA + off);
            }
#pragma unroll
            for (int p = 0; p < 4; p++) {
                uint32_t r[4];
                uint32_t off = SWZ((uint32_t)((wn * 64 + p * 16 + bnrow) * 128 + kk * 32 + bkb));
                ldsm4(r, sB + off);
                bf[2 * p + 0][0] = r[0]; bf[2 * p + 0][1] = r[1];
                bf[2 * p + 1][0] = r[2]; bf[2 * p + 1][1] = r[3];
            }
#pragma unroll
            for (int mi = 0; mi < 2; mi++)
#pragma unroll
                for (int ni = 0; ni < 8; ni++)
                    mma_f16(acc[mi][ni], af[mi], bf[ni]);
        }
        __syncthreads();
    }

    // Epilogue: bias + BN + ReLU, float2 stores
    const int tr = lane >> 2, tq = lane & 3;
#pragma unroll
    for (int mi = 0; mi < 2; mi++) {
        int row0 = bm + wm * 32 + mi * 16 + tr;
#pragma unroll
        for (int ni = 0; ni < 8; ni++) {
            int col = wn * 64 + ni * 8 + 2 * tq;   // 0..255 (== global col)
            float s0 = sScale[col],   s1 = sScale[col + 1];
            float h0 = sShift[col],   h1 = sShift[col + 1];
            float bb0 = sBias[col],   bb1 = sBias[col + 1];
            float2 v0, v1;
            v0.x = fmaxf((acc[mi][ni][0] + bb0) * s0 + h0, 0.f);
            v0.y = fmaxf((acc[mi][ni][1] + bb1) * s1 + h1, 0.f);
            v1.x = fmaxf((acc[mi][ni][2] + bb0) * s0 + h0, 0.f);
            v1.y = fmaxf((acc[mi][ni][3] + bb1) * s1 + h1, 0.f);
            *(float2*)&C[(size_t)row0 * DO + col]       = v0;
            *(float2*)&C[(size_t)(row0 + 8) * DO + col] = v1;
        }
    }
}

// ---------------------------------------------------------------------------
// Fused 3-NN + inverse-distance-weighted gather + accumulate (proven R1).
// ---------------------------------------------------------------------------
#define KNN_THREADS 256
#define KNN_SMEM (N1 * 16 + KNN_THREADS * 3 * 4 * 2)

__global__ __launch_bounds__(KNN_THREADS)
void knn_interp_kernel(const float* __restrict__ xyz2,
                       const float* __restrict__ xyz1,
                       float* __restrict__ out)
{
    extern __shared__ float smem[];
    float4* sx = (float4*)smem;
    float*  sw = smem + N1 * 4;
    int*    si = (int*)(sw + KNN_THREADS * 3);

    const int b   = blockIdx.y;
    const int tid = threadIdx.x;
    const int t   = blockIdx.x * KNN_THREADS + tid;

    for (int i = tid; i < N1; i += KNN_THREADS) {
        const float* p = &xyz1[((size_t)b * N1 + i) * 3];
        float x = p[0], y = p[1], z = p[2];
        sx[i] = make_float4(-2.f * x, -2.f * y, -2.f * z, x * x + y * y + z * z);
    }
    __syncthreads();

    const float* tp = &xyz2[((size_t)b * N2 + t) * 3];
    const float txx = tp[0], tyy = tp[1], tzz = tp[2];

    float k0 = 3.4e38f, k1 = 3.4e38f, k2 = 3.4e38f;
    int   i0 = 0, i1 = 0, i2 = 0;

#pragma unroll 4
    for (int s = 0; s < N1; s++) {
        float4 p = sx[s];
        float key = fmaf(p.x, txx, fmaf(p.y, tyy, fmaf(p.z, tzz, p.w)));
        if (key < k2) {
            if (key < k0)      { k2 = k1; i2 = i1; k1 = k0; i1 = i0; k0 = key; i0 = s; }
            else if (key < k1) { k2 = k1; i2 = i1; k1 = key; i1 = s; }
            else               { k2 = key; i2 = s; }
        }
    }

    float tt = txx * txx + tyy * tyy + tzz * tzz;
    float d0 = k0 + tt, d1 = k1 + tt, d2 = k2 + tt;
    float w0 = 1.f / (d0 + 1e-8f);
    float w1 = 1.f / (d1 + 1e-8f);
    float w2 = 1.f / (d2 + 1e-8f);
    float inv = 1.f / (w0 + w1 + w2);
    sw[tid * 3 + 0] = w0 * inv;
    sw[tid * 3 + 1] = w1 * inv;
    sw[tid * 3 + 2] = w2 * inv;
    si[tid * 3 + 0] = i0;
    si[tid * 3 + 1] = i1;
    si[tid * 3 + 2] = i2;
    __syncthreads();

    const int warp = tid >> 5, lane = tid & 31;
    const float* fb = g_feats1 + (size_t)b * N1 * DO;

    for (int j = 0; j < 32; j++) {
        int local = warp * 32 + j;
        float ww0 = sw[local * 3 + 0];
        float ww1 = sw[local * 3 + 1];
        float ww2 = sw[local * 3 + 2];
        int   a0  = si[local * 3 + 0];
        int   a1  = si[local * 3 + 1];
        int   a2  = si[local * 3 + 2];
        const float4* f0 = (const float4*)(fb + (size_t)a0 * DO);
        const float4* f1 = (const float4*)(fb + (size_t)a1 * DO);
        const float4* f2 = (const float4*)(fb + (size_t)a2 * DO);
        int tgt = blockIdx.x * KNN_THREADS + local;
        float4* o = (float4*)(out + ((size_t)b * N2 + tgt) * DO);
#pragma unroll
        for (int c = 0; c < 2; c++) {
            int ci = lane * 2 + c;
            float4 va = f0[ci], vb = f1[ci], vc = f2[ci], vo = o[ci];
            vo.x += ww0 * va.x + ww1 * vb.x + ww2 * vc.x;
            vo.y += ww0 * va.y + ww1 * vb.y + ww2 * vc.y;
            vo.z += ww0 * va.z + ww1 * vb.z + ww2 * vc.z;
            vo.w += ww0 * va.w + ww1 * vb.w + ww2 * vc.w;
            o[ci] = vo;
        }
    }
}

// ---------------------------------------------------------------------------
extern "C" void kernel_launch(void* const* d_in, const int* in_sizes, int n_in,
                              void* d_out, int out_size)
{
    const float* xyz1    = (const float*)d_in[0];
    const float* points1 = (const float*)d_in[1];
    const float* xyz2    = (const float*)d_in[2];
    const float* points2 = (const float*)d_in[3];
    const float* W1  = (const float*)d_in[4];
    const float* b1  = (const float*)d_in[5];
    const float* g1  = (const float*)d_in[6];
    const float* be1 = (const float*)d_in[7];
    const float* m1  = (const float*)d_in[8];
    const float* v1  = (const float*)d_in[9];
    const float* W2  = (const float*)d_in[10];
    const float* b2  = (const float*)d_in[11];
    const float* g2  = (const float*)d_in[12];
    const float* be2 = (const float*)d_in[13];
    const float* m2  = (const float*)d_in[14];
    const float* v2  = (const float*)d_in[15];
    float* out = (float*)d_out;

    float* feats1;
    __half *a1f, *a2f, *w1f, *w2f;
    cudaGetSymbolAddress((void**)&feats1, g_feats1);
    cudaGetSymbolAddress((void**)&a1f, gA1f);
    cudaGetSymbolAddress((void**)&a2f, gA2f);
    cudaGetSymbolAddress((void**)&w1f, gW1f);
    cudaGetSymbolAddress((void**)&w2f, gW2f);

    // fp32 -> fp16 converts
    cvt_half_kernel<<<2048, 256>>>(points1, a1f, M1 * D1 / 4);
    cvt_half_kernel<<<4096, 256>>>(points2, a2f, M2 * D2 / 4);
    cvt_half_kernel<<<128,  256>>>(W1, w1f, DO * D1 / 4);
    cvt_half_kernel<<<64,   256>>>(W2, w2f, DO * D2 / 4);

    cudaFuncSetAttribute(gemm_mma_kernel,
                         cudaFuncAttributeMaxDynamicSharedMemorySize, GEMM_DSMEM);

    // K1: feats1 = relu(bn(points1 @ W1^T + b1))   [16384, 256]
    gemm_mma_kernel<<<M1 / 128, 512, GEMM_DSMEM>>>(a1f, w1f,
                                                   b1, g1, be1, m1, v1,
                                                   feats1, D1);
    // K2: out = relu(bn(points2 @ W2^T + b2))      [65536, 256]
    gemm_mma_kernel<<<M2 / 128, 512, GEMM_DSMEM>>>(a2f, w2f,
                                                   b2, g2, be2, m2, v2,
                                                   out, D2);

    // K3: out += interpolate3(xyz2 <- xyz1, feats1)
    cudaFuncSetAttribute(knn_interp_kernel,
                         cudaFuncAttributeMaxDynamicSharedMemorySize, KNN_SMEM);
    dim3 grid(N2 / KNN_THREADS, BATCH);
    knn_interp_kernel<<<grid, KNN_THREADS, KNN_SMEM>>>(xyz2, xyz1, out);
}

// round 9
// speedup vs baseline: 1.5592x; 1.0395x over previous
#include <cuda_runtime.h>
#include <cuda_fp16.h>
#include <cstdint>
#include <math.h>

// Problem constants (fixed shapes from setup_inputs)
#define BATCH   4
#define N1      4096
#define N2      16384
#define D1      512
#define D2      256
#define DO      256
#define M1      (BATCH * N1)   // 16384
#define M2      (BATCH * N2)   // 65536

// ---------------------------------------------------------------------------
// Device scratch (allocation-free rule: __device__ globals)
// ---------------------------------------------------------------------------
__device__ float g_feats1[M1 * DO];                         // 16 MB
__device__ __align__(16) __half gA1f[M1 * D1];              // 16 MB
__device__ __align__(16) __half gA2f[M2 * D2];              // 32 MB
__device__ __align__(16) __half gW1f[DO * D1];
__device__ __align__(16) __half gW2f[DO * D2];
__device__ float4 g_knnw[M2];                               // weights (w0,w1,w2,-)
__device__ int4   g_knni[M2];                               // global feats1 row idx

// ---------------------------------------------------------------------------
// Helpers
// ---------------------------------------------------------------------------
__device__ __forceinline__ uint32_t smem_u32(const void* p) {
    uint32_t a;
    asm("{ .reg .u64 t; cvta.to.shared.u64 t, %1; cvt.u32.u64 %0, t; }"
        : "=r"(a) : "l"(p));
    return a;
}

#define SWZ(o) ((o) ^ (((o) >> 3) & 0x70))

#define CP16(dst, src) \
    asm volatile("cp.async.cg.shared.global [%0], [%1], 16;" :: "r"(dst), "l"(src) : "memory")
#define CP_COMMIT() asm volatile("cp.async.commit_group;" ::: "memory")
#define CP_WAIT0()  asm volatile("cp.async.wait_group 0;" ::: "memory")
#define CP_WAIT1()  asm volatile("cp.async.wait_group 1;" ::: "memory")

__device__ __forceinline__ void ldsm4(uint32_t r[4], uint32_t addr) {
    asm volatile("ldmatrix.sync.aligned.m8n8.x4.shared.b16 {%0,%1,%2,%3}, [%4];"
        : "=r"(r[0]), "=r"(r[1]), "=r"(r[2]), "=r"(r[3]) : "r"(addr));
}
__device__ __forceinline__ void mma_f16(float d[4], const uint32_t a[4], const uint32_t b[2]) {
    asm volatile("mma.sync.aligned.m16n8k16.row.col.f32.f16.f16.f32 "
        "{%0,%1,%2,%3}, {%4,%5,%6,%7}, {%8,%9}, {%0,%1,%2,%3};"
        : "+f"(d[0]), "+f"(d[1]), "+f"(d[2]), "+f"(d[3])
        : "r"(a[0]), "r"(a[1]), "r"(a[2]), "r"(a[3]), "r"(b[0]), "r"(b[1]));
}

// ---------------------------------------------------------------------------
// fp32 -> fp16 convert (round-to-nearest)
// ---------------------------------------------------------------------------
__global__ __launch_bounds__(256)
void cvt_half_kernel(const float* __restrict__ x, __half* __restrict__ y, int n4)
{
    int i = blockIdx.x * blockDim.x + threadIdx.x;
    int stride = gridDim.x * blockDim.x;
    for (; i < n4; i += stride) {
        float4 v = ((const float4*)x)[i];
        ((__half2*)y)[2 * i + 0] = __floats2half2_rn(v.x, v.y);
        ((__half2*)y)[2 * i + 1] = __floats2half2_rn(v.z, v.w);
    }
}

// ---------------------------------------------------------------------------
// 3-NN phase 1: per-target weights + global feats1 row indices.
// Rank key = ||s||^2 - 2 t.s (order-invariant shift of true distance).
// ---------------------------------------------------------------------------
#define KNN_THREADS 256
#define KNN_SMEM (N1 * 16)

__global__ __launch_bounds__(KNN_THREADS)
void knn_phase1_kernel(const float* __restrict__ xyz2,   // targets [B,N2,3]
                       const float* __restrict__ xyz1)   // sources [B,N1,3]
{
    extern __shared__ float smem[];
    float4* sx = (float4*)smem;

    const int b   = blockIdx.y;
    const int tid = threadIdx.x;
    const int t   = blockIdx.x * KNN_THREADS + tid;

    for (int i = tid; i < N1; i += KNN_THREADS) {
        const float* p = &xyz1[((size_t)b * N1 + i) * 3];
        float x = p[0], y = p[1], z = p[2];
        sx[i] = make_float4(-2.f * x, -2.f * y, -2.f * z, x * x + y * y + z * z);
    }
    __syncthreads();

    const float* tp = &xyz2[((size_t)b * N2 + t) * 3];
    const float txx = tp[0], tyy = tp[1], tzz = tp[2];

    float k0 = 3.4e38f, k1 = 3.4e38f, k2 = 3.4e38f;
    int   i0 = 0, i1 = 0, i2 = 0;

#pragma unroll 4
    for (int s = 0; s < N1; s++) {
        float4 p = sx[s];
        float key = fmaf(p.x, txx, fmaf(p.y, tyy, fmaf(p.z, tzz, p.w)));
        if (key < k2) {
            if (key < k0)      { k2 = k1; i2 = i1; k1 = k0; i1 = i0; k0 = key; i0 = s; }
            else if (key < k1) { k2 = k1; i2 = i1; k1 = key; i1 = s; }
            else               { k2 = key; i2 = s; }
        }
    }

    float tt = txx * txx + tyy * tyy + tzz * tzz;
    float w0 = 1.f / (k0 + tt + 1e-8f);
    float w1 = 1.f / (k1 + tt + 1e-8f);
    float w2 = 1.f / (k2 + tt + 1e-8f);
    float inv = 1.f / (w0 + w1 + w2);

    int g = b * N2 + t;
    g_knnw[g] = make_float4(w0 * inv, w1 * inv, w2 * inv, 0.f);
    g_knni[g] = make_int4(b * N1 + i0, b * N1 + i1, b * N1 + i2, 0);
}

// ---------------------------------------------------------------------------
// fp16 mma.sync GEMM + BN + ReLU, CTA tile 128x256, 512 threads (16 warps 4x4),
// warp tile 32x64. K-chunk 64 fp16 (SW128). Double-buffered cp.async.
// FUSE_INTERP: epilogue additionally adds 3-NN weighted gather from g_feats1.
// ---------------------------------------------------------------------------
#define STAGE 49152u
#define GEMM_DSMEM (2 * 49152 + 1024)

__device__ __forceinline__ void load_chunk(int tid, int bm, int K,
                                           uint32_t base, int c,
                                           const __half* __restrict__ A,
                                           const __half* __restrict__ B)
{
    uint32_t sb = base + (uint32_t)(c & 1) * STAGE;
    int kc = c << 6;
    for (int i = tid; i < 1024; i += 512) {
        int row = i >> 3, seg = i & 7;
        uint32_t off = SWZ((uint32_t)(row * 128 + seg * 16));
        CP16(sb + off, (const char*)(A + (size_t)(bm + row) * K + kc + seg * 8));
    }
    for (int i = tid; i < 2048; i += 512) {
        int row = i >> 3, seg = i & 7;
        uint32_t off = SWZ((uint32_t)(row * 128 + seg * 16));
        CP16(sb + 16384u + off, (const char*)(B + (size_t)row * K + kc + seg * 8));
    }
    CP_COMMIT();
}

template<bool FUSE_INTERP>
__global__ __launch_bounds__(512, 1)
void gemm_mma_kernel(const __half* __restrict__ A,
                     const __half* __restrict__ B,
                     const float* __restrict__ bias,
                     const float* __restrict__ gamma,
                     const float* __restrict__ beta,
                     const float* __restrict__ mean,
                     const float* __restrict__ var,
                     float* __restrict__ C, int K)
{
    extern __shared__ char dsm[];
    __shared__ float sScale[DO], sShift[DO], sBias[DO];

    const int tid  = threadIdx.x;
    const int wid  = tid >> 5;
    const int lane = tid & 31;
    const int wm   = wid >> 2;
    const int wn   = wid & 3;
    const int bm   = blockIdx.x * 128;
    const int NC   = K >> 6;
    uint32_t base  = (smem_u32(dsm) + 1023u) & ~1023u;

    if (tid < DO) {
        float sc = gamma[tid] * rsqrtf(var[tid] + 1e-5f);
        sScale[tid] = sc;
        sShift[tid] = beta[tid] - mean[tid] * sc;
        sBias[tid]  = bias[tid];
    }

    float acc[2][8][4];
#pragma unroll
    for (int mi = 0; mi < 2; mi++)
#pragma unroll
        for (int ni = 0; ni < 8; ni++)
#pragma unroll
            for (int e = 0; e < 4; e++) acc[mi][ni][e] = 0.f;

    load_chunk(tid, bm, K, base, 0, A, B);

    const int arow  = wm * 32 + (lane & 15);
    const int acolb = (lane >> 4) * 16;
    const int g     = lane >> 3;
    const int bnrow = (g >> 1) * 8 + (lane & 7);
    const int bkb   = (g & 1) * 16;

    for (int c = 0; c < NC; c++) {
        if (c + 1 < NC) {
            load_chunk(tid, bm, K, base, c + 1, A, B);
            CP_WAIT1();
        } else {
            CP_WAIT0();
        }
        __syncthreads();

        uint32_t sb = base + (uint32_t)(c & 1) * STAGE;
        uint32_t sA = sb, sB = sb + 16384u;

#pragma unroll
        for (int kk = 0; kk < 4; kk++) {
            uint32_t af[2][4], bf[8][2];
#pragma unroll
            for (int mi = 0; mi < 2; mi++) {
                uint32_t off = SWZ((uint32_t)((arow + mi * 16) * 128 + kk * 32 + acolb));
                ldsm4(af[mi], sA + off);
            }
#pragma unroll
            for (int p = 0; p < 4; p++) {
                uint32_t r[4];
                uint32_t off = SWZ((uint32_t)((wn * 64 + p * 16 + bnrow) * 128 + kk * 32 + bkb));
                ldsm4(r, sB + off);
                bf[2 * p + 0][0] = r[0]; bf[2 * p + 0][1] = r[1];
                bf[2 * p + 1][0] = r[2]; bf[2 * p + 1][1] = r[3];
            }
#pragma unroll
            for (int mi = 0; mi < 2; mi++)
#pragma unroll
                for (int ni = 0; ni < 8; ni++)
                    mma_f16(acc[mi][ni], af[mi], bf[ni]);
        }
        __syncthreads();
    }

    // Epilogue: bias + BN + ReLU (+ optional fused 3-NN interp add)
    const int tr = lane >> 2, tq = lane & 3;
#pragma unroll
    for (int mi = 0; mi < 2; mi++) {
#pragma unroll
        for (int half = 0; half < 2; half++) {
            int row = bm + wm * 32 + mi * 16 + tr + half * 8;   // global output row
            float4 w4; int4 id4;
            const float *f0 = nullptr, *f1 = nullptr, *f2 = nullptr;
            if (FUSE_INTERP) {
                w4  = g_knnw[row];
                id4 = g_knni[row];
                f0 = g_feats1 + (size_t)id4.x * DO;
                f1 = g_feats1 + (size_t)id4.y * DO;
                f2 = g_feats1 + (size_t)id4.z * DO;
            }
            float* outRow = C + (size_t)row * DO;
#pragma unroll
            for (int ni = 0; ni < 8; ni++) {
                int col = wn * 64 + ni * 8 + 2 * tq;
                int e = half * 2;
                float2 v;
                v.x = fmaxf((acc[mi][ni][e + 0] + sBias[col])     * sScale[col]     + sShift[col],     0.f);
                v.y = fmaxf((acc[mi][ni][e + 1] + sBias[col + 1]) * sScale[col + 1] + sShift[col + 1], 0.f);
                if (FUSE_INTERP) {
                    float2 e0 = *(const float2*)(f0 + col);
                    float2 e1 = *(const float2*)(f1 + col);
                    float2 e2 = *(const float2*)(f2 + col);
                    v.x += w4.x * e0.x + w4.y * e1.x + w4.z * e2.x;
                    v.y += w4.x * e0.y + w4.y * e1.y + w4.z * e2.y;
                }
                *(float2*)(outRow + col) = v;
            }
        }
    }
}

// ---------------------------------------------------------------------------
extern "C" void kernel_launch(void* const* d_in, const int* in_sizes, int n_in,
                              void* d_out, int out_size)
{
    const float* xyz1    = (const float*)d_in[0];
    const float* points1 = (const float*)d_in[1];
    const float* xyz2    = (const float*)d_in[2];
    const float* points2 = (const float*)d_in[3];
    const float* W1  = (const float*)d_in[4];
    const float* b1  = (const float*)d_in[5];
    const float* g1  = (const float*)d_in[6];
    const float* be1 = (const float*)d_in[7];
    const float* m1  = (const float*)d_in[8];
    const float* v1  = (const float*)d_in[9];
    const float* W2  = (const float*)d_in[10];
    const float* b2  = (const float*)d_in[11];
    const float* g2  = (const float*)d_in[12];
    const float* be2 = (const float*)d_in[13];
    const float* m2  = (const float*)d_in[14];
    const float* v2  = (const float*)d_in[15];
    float* out = (float*)d_out;

    float* feats1;
    __half *a1f, *a2f, *w1f, *w2f;
    cudaGetSymbolAddress((void**)&feats1, g_feats1);
    cudaGetSymbolAddress((void**)&a1f, gA1f);
    cudaGetSymbolAddress((void**)&a2f, gA2f);
    cudaGetSymbolAddress((void**)&w1f, gW1f);
    cudaGetSymbolAddress((void**)&w2f, gW2f);

    // 3-NN weights/indices (independent of GEMMs; run first)
    cudaFuncSetAttribute(knn_phase1_kernel,
                         cudaFuncAttributeMaxDynamicSharedMemorySize, KNN_SMEM);
    {
        dim3 grid(N2 / KNN_THREADS, BATCH);
        knn_phase1_kernel<<<grid, KNN_THREADS, KNN_SMEM>>>(xyz2, xyz1);
    }

    // fp32 -> fp16 converts
    cvt_half_kernel<<<2048, 256>>>(points1, a1f, M1 * D1 / 4);
    cvt_half_kernel<<<4096, 256>>>(points2, a2f, M2 * D2 / 4);
    cvt_half_kernel<<<128,  256>>>(W1, w1f, DO * D1 / 4);
    cvt_half_kernel<<<64,   256>>>(W2, w2f, DO * D2 / 4);

    cudaFuncSetAttribute(gemm_mma_kernel<false>,
                         cudaFuncAttributeMaxDynamicSharedMemorySize, GEMM_DSMEM);
    cudaFuncSetAttribute(gemm_mma_kernel<true>,
                         cudaFuncAttributeMaxDynamicSharedMemorySize, GEMM_DSMEM);

    // K1: feats1 = relu(bn(points1 @ W1^T + b1))   [16384, 256]
    gemm_mma_kernel<false><<<M1 / 128, 512, GEMM_DSMEM>>>(a1f, w1f,
                                                          b1, g1, be1, m1, v1,
                                                          feats1, D1);
    // K2 (+fused interp): out = relu(bn(points2 @ W2^T + b2)) + interp3(feats1)
    gemm_mma_kernel<true><<<M2 / 128, 512, GEMM_DSMEM>>>(a2f, w2f,
                                                         b2, g2, be2, m2, v2,
                                                         out, D2);
}